// round 17
// baseline (speedup 1.0000x reference)
#include <cuda_runtime.h>
#include <cuda_bf16.h>
#include <cstdint>

// PersistenceLandscapeLayer — cluster-resident fun_value version.
// Cluster of 2 CTAs per batch row: each CTA streams N/2 floats (128KB) of the
// row into smem (coalesced), then all gathers are ld.shared::cluster (DSMEM).
// Warp-private compaction (R10) + per-lane-cell scan; smem tree merge; the
// 2 per-CTA partials merged by the last CTA of the row (g_cnt protocol).
//
// tent(t) = max(min(t-b,d-t),0) == max(hw-|t-c|,0); clamp dropped (top-4 regs
// start at 0 and stay >= 0, so negative candidates never enter a chain).

constexpr int TT    = 32;
constexpr int D_HOM = 2;
constexpr int KMAX  = 4;
constexpr int NCELL = D_HOM * TT;           // 64
constexpr int NTH   = 1024;
constexpr int NWARP = NTH / 32;             // 32
constexpr int PPW   = 64;                   // pairs per warp per tile
constexpr int TILE  = NWARP * PPW;          // 2048 pairs per CTA per tile
constexpr int MAXB  = 128;
constexpr unsigned FULL = 0xffffffffu;

__device__ float4 g_part[MAXB * 2 * NCELL]; // per-(row, cluster-rank) partials
__device__ int    g_cnt[MAXB];              // zero-init; reset by last CTA

#define INS4(r0,r1,r2,r3,v) do { float _x;                         \
    _x = fmaxf(r0, v); v = fminf(r0, v); r0 = _x;                  \
    _x = fmaxf(r1, v); v = fminf(r1, v); r1 = _x;                  \
    _x = fmaxf(r2, v); v = fminf(r2, v); r2 = _x;                  \
    r3 = fmaxf(r3, v); } while (0)

#define BMERGE(a0,a1,a2,a3,b0,b1,b2,b3) do {                       \
    float _l0 = fmaxf(a0, b3), _l1 = fmaxf(a1, b2);                \
    float _l2 = fmaxf(a2, b1), _l3 = fmaxf(a3, b0);                \
    float _x0 = fmaxf(_l0, _l2), _x2 = fminf(_l0, _l2);            \
    float _x1 = fmaxf(_l1, _l3), _x3 = fminf(_l1, _l3);            \
    a0 = fmaxf(_x0, _x1); a1 = fminf(_x0, _x1);                    \
    a2 = fmaxf(_x2, _x3); a3 = fminf(_x2, _x3); } while (0)

__device__ __forceinline__ float4 bmerge4(float4 a, float4 b) {
    BMERGE(a.x, a.y, a.z, a.w, b.x, b.y, b.z, b.w);
    return a;
}

__device__ __forceinline__ unsigned smem_u32(const void* p) {
    unsigned a;
    asm("{ .reg .u64 t; cvta.to.shared.u64 t, %1; cvt.u32.u64 %0, t; }"
        : "=r"(a) : "l"(p));
    return a;
}

// Read fun[idx] from whichever cluster CTA holds it (CTA r holds half r).
__device__ __forceinline__ float cfun(unsigned base, int idx, int HALF) {
    unsigned rk = (unsigned)(idx >= HALF);
    unsigned a  = base + ((unsigned)idx - rk * (unsigned)HALF) * 4u;
    unsigned ra;
    asm("mapa.shared::cluster.u32 %0, %1, %2;" : "=r"(ra) : "r"(a), "r"(rk));
    float v;
    asm volatile("ld.shared::cluster.f32 %0, [%1];" : "=f"(v) : "r"(ra));
    return v;
}

__global__ __launch_bounds__(NTH, 1) __cluster_dims__(2, 1, 1)
void pl_cluster(const float* __restrict__ fun,
                const int*   __restrict__ bidx,
                const int*   __restrict__ didx,
                const int*   __restrict__ pdim,
                float*       __restrict__ out,
                int N, int P)
{
    extern __shared__ __align__(16) char smem[];
    const int HALF = N >> 1;
    const int PC   = P >> 1;                 // pairs per CTA
    float*  sfun = (float*)smem;                                        // HALF floats
    float2* wl   = (float2*)(smem + (size_t)HALF * 4);                  // [NWARP][2][PPW]
    float4* mbuf = (float4*)(smem + (size_t)HALF * 4
                             + (size_t)NWARP * D_HOM * PPW * 8);        // [NWARP][NCELL]
    __shared__ int isLast;

    const int tid  = threadIdx.x;
    const int lane = tid & 31;
    const int wp   = tid >> 5;
    const int rank = blockIdx.x;             // 0/1 within cluster
    const int bb   = blockIdx.y;             // batch row

    // ---- Stream own half of the row into smem (coalesced float4) ----
    {
        const float4* src = (const float4*)(fun + (size_t)bb * N + (size_t)rank * HALF);
        float4*       dst = (float4*)sfun;
        const int nq = HALF >> 2;
        #pragma unroll 4
        for (int i = tid; i < nq; i += NTH) dst[i] = src[i];
    }
    __syncthreads();
    asm volatile("barrier.cluster.arrive.aligned;" ::: "memory");
    asm volatile("barrier.cluster.wait.aligned;" ::: "memory");   // both halves ready

    const unsigned sfa = smem_u32(sfun);
    const int* brow = bidx + (size_t)bb * P;
    const int* drow = didx + (size_t)bb * P;
    const int* prow = pdim + (size_t)bb * P;

    const float tv = (float)(lane + 1) * (1.0f / (float)TT);
    float A0=0.f,A1=0.f,A2=0.f,A3=0.f;   // dim0, even k
    float B0=0.f,B1=0.f,B2=0.f,B3=0.f;   // dim0, odd k
    float C0=0.f,C1=0.f,C2=0.f,C3=0.f;   // dim1, even k
    float D0=0.f,D1=0.f,D2=0.f,D3=0.f;   // dim1, odd k

    float2 (*mylst)[PPW] = (float2(*)[PPW])(wl + (size_t)wp * D_HOM * PPW);

    const int pbeg = rank * PC, pend = rank * PC + PC;
    for (int base = pbeg; base < pend; base += TILE) {
        // ---- Gather 2 pairs per lane via cluster shared memory ----
        const int p0 = base + wp * PPW + 2 * lane;
        bool act0 = (p0     < pend);
        bool act1 = (p0 + 1 < pend);
        int bi0 = 0, bi1 = 0, di0 = 0, di1 = 0, dm0 = 0, dm1 = 0;
        if (act1) {
            int2 b2 = *(const int2*)(brow + p0);
            int2 d2 = *(const int2*)(drow + p0);
            int2 m2 = *(const int2*)(prow + p0);
            bi0 = b2.x; bi1 = b2.y; di0 = d2.x; di1 = d2.y; dm0 = m2.x; dm1 = m2.y;
        } else if (act0) {
            bi0 = brow[p0]; di0 = drow[p0]; dm0 = prow[p0];
        }
        float bv0 = 0.f, dv0 = 0.f, bv1 = 0.f, dv1 = 0.f;
        if (act0) { bv0 = cfun(sfa, bi0, HALF); dv0 = cfun(sfa, di0, HALF); }
        if (act1) { bv1 = cfun(sfa, bi1, HALF); dv1 = cfun(sfa, di1, HALF); }

        bool keep0 = act0 && (dv0 > bv0);
        bool keep1 = act1 && (dv1 > bv1);
        float c0 = (bv0 + dv0) * 0.5f, h0 = (dv0 - bv0) * 0.5f;
        float c1 = (bv1 + dv1) * 0.5f, h1 = (dv1 - bv1) * 0.5f;

        // ---- Warp-private compaction (register counters, no atomics) ----
        int n0 = 0, n1 = 0;
        {
            const unsigned lt = (1u << lane) - 1u;
            unsigned m;
            m = __ballot_sync(FULL, keep0 && dm0 == 0);
            if (keep0 && dm0 == 0) mylst[0][n0 + __popc(m & lt)] = make_float2(c0, h0);
            n0 += __popc(m);
            m = __ballot_sync(FULL, keep1 && dm1 == 0);
            if (keep1 && dm1 == 0) mylst[0][n0 + __popc(m & lt)] = make_float2(c1, h1);
            n0 += __popc(m);
            m = __ballot_sync(FULL, keep0 && dm0 == 1);
            if (keep0 && dm0 == 1) mylst[1][n1 + __popc(m & lt)] = make_float2(c0, h0);
            n1 += __popc(m);
            m = __ballot_sync(FULL, keep1 && dm1 == 1);
            if (keep1 && dm1 == 1) mylst[1][n1 + __popc(m & lt)] = make_float2(c1, h1);
            n1 += __popc(m);
        }
        __syncwarp();

        // ---- Scan own lists: lane owns (dim0,t=lane) and (dim1,t=lane) ----
        const int kmax = max(n0, n1);
        for (int k = 0; k < kmax; k += 2) {
            const int k1 = min(k + 1, PPW - 1);
            float2 qa0 = mylst[0][k];
            float2 qb0 = mylst[0][k1];
            float2 qa1 = mylst[1][k];
            float2 qb1 = mylst[1][k1];
            float ma0 = qa0.y - fabsf(tv - qa0.x); ma0 = (k     < n0) ? ma0 : -1.0f;
            float mb0 = qb0.y - fabsf(tv - qb0.x); mb0 = (k + 1 < n0) ? mb0 : -1.0f;
            float ma1 = qa1.y - fabsf(tv - qa1.x); ma1 = (k     < n1) ? ma1 : -1.0f;
            float mb1 = qb1.y - fabsf(tv - qb1.x); mb1 = (k + 1 < n1) ? mb1 : -1.0f;
            INS4(A0, A1, A2, A3, ma0);
            INS4(B0, B1, B2, B3, mb0);
            INS4(C0, C1, C2, C3, ma1);
            INS4(D0, D1, D2, D3, mb1);
        }
        __syncwarp();                        // lists reusable next tile
    }
    // Peer gathers of my sfun are done after my gather loop + peer's; split
    // cluster barrier: arrive now, wait at the end (overlaps scan epilogue).
    asm volatile("barrier.cluster.arrive.aligned;" ::: "memory");

    BMERGE(A0, A1, A2, A3, B0, B1, B2, B3);  // dim0 in A
    BMERGE(C0, C1, C2, C3, D0, D1, D2, D3);  // dim1 in C

    mbuf[(size_t)wp * NCELL + lane]      = make_float4(A0, A1, A2, A3);
    mbuf[(size_t)wp * NCELL + 32 + lane] = make_float4(C0, C1, C2, C3);
    __syncthreads();

    // ---- Combine 32 warp partials per cell; write per-CTA partial ----
    if (tid < NCELL) {
        float4 r = mbuf[tid];
        #pragma unroll 4
        for (int w = 1; w < NWARP; ++w)
            r = bmerge4(r, mbuf[(size_t)w * NCELL + tid]);
        g_part[((size_t)bb * 2 + rank) * NCELL + tid] = r;
        __threadfence();
    }
    __syncthreads();

    // ---- Last CTA of this row merges the 2 partials ----
    if (tid == 0) {
        int v = atomicAdd(&g_cnt[bb], 1);
        isLast = (v == 1);
        if (isLast) g_cnt[bb] = 0;           // reset for next graph replay
    }
    __syncthreads();

    if (isLast) {
        if (tid == 0) __threadfence();
        __syncthreads();
        if (tid < NCELL) {
            const float4* src = &g_part[(size_t)bb * 2 * NCELL + tid];
            float4 r = bmerge4(__ldcg(src), __ldcg(src + NCELL));
            ((float4*)out)[(size_t)bb * NCELL + tid] = r;
        }
    }
    asm volatile("barrier.cluster.wait.aligned;" ::: "memory");   // exit hazard
}

extern "C" void kernel_launch(void* const* d_in, const int* in_sizes, int n_in,
                              void* d_out, int out_size)
{
    const float* fun = (const float*)d_in[0];
    const int*   bi  = (const int*)  d_in[1];
    const int*   di  = (const int*)  d_in[2];
    const int*   pd  = (const int*)  d_in[3];
    float*       out = (float*)d_out;

    int B = out_size / (D_HOM * TT * KMAX);
    int N = in_sizes[0] / B;
    int P = in_sizes[1] / B;

    size_t smembytes = (size_t)(N / 2) * 4
                     + (size_t)NWARP * D_HOM * PPW * 8
                     + (size_t)NWARP * NCELL * 16;   // 196608 for N=65536

    cudaFuncSetAttribute(pl_cluster,
                         cudaFuncAttributeMaxDynamicSharedMemorySize,
                         (int)smembytes);

    dim3 g(2, B);
    pl_cluster<<<g, NTH, smembytes>>>(fun, bi, di, pd, out, N, P);
}